// round 15
// baseline (speedup 1.0000x reference)
#include <cuda_runtime.h>
#include <cuda_fp16.h>
#include <cuda_bf16.h>

#define NN 100000
#define NE 1600000
#define NG 512
#define H1C 64
#define H2C 128
#define OUTC 2
#define CAP 128          // bucket capacity per node (max in-degree guard)
#define CSH 7            // log2(CAP)
#define NTILES 6250      // NN / 16

#define PDL_WAIT asm volatile("griddepcontrol.wait;" ::: "memory")
#define PDL_FIRE asm volatile("griddepcontrol.launch_dependents;")

// ---------------- scratch (__device__ globals) ----------------
__device__ __align__(16) int     g_icnt[NN];         // in-degree
__device__ __align__(16) int     g_csrc[NN * CAP];   // bucket CSR: src per slot
__device__ __align__(16) float   g_xs4 [NN * 4];     // {d*x0, d*x1, d*x2, d}
__device__ __align__(16) float   g_a4  [NN * 4];     // {d*agg0, d*agg1, d*agg2, d}
__device__ __align__(16) __half2 g_h1h [NN * 32];    // fp16 dinv-scaled relu(l1)
__device__ __align__(16) __half2 g_aggh2[NN * 32];   // fp16 layer-2 aggregate
__device__ __align__(16) float   g_pool[NG * H2C];
__device__ __align__(16) float   g_cnt [NG];

__device__ __forceinline__ void red_add_f(float* addr, float v) {
    asm volatile("red.global.add.f32 [%0], %1;" :: "l"(addr), "f"(v) : "memory");
}

// -------------------------------- zero in-degree counters
__global__ void k_zero() {
    PDL_FIRE;
    int i = blockIdx.x * blockDim.x + threadIdx.x;
    if (i < NN / 4) ((int4*)g_icnt)[i] = make_int4(0, 0, 0, 0);
}

// ------------- fused count + bucket fill (ONE edge pass)
__global__ void k_cf(const int* __restrict__ src, const int* __restrict__ dst) {
    int i = blockIdx.x * blockDim.x + threadIdx.x;
    int4 d4 = make_int4(0, 0, 0, 0), s4 = make_int4(0, 0, 0, 0);
    bool ok = (i < NE / 4);
    if (ok) { d4 = ((const int4*)dst)[i]; s4 = ((const int4*)src)[i]; }
    PDL_WAIT; PDL_FIRE;
    if (!ok) return;
    int r;
    r = atomicAdd(&g_icnt[d4.x], 1); if (r < CAP) g_csrc[(d4.x << CSH) + r] = s4.x;
    r = atomicAdd(&g_icnt[d4.y], 1); if (r < CAP) g_csrc[(d4.y << CSH) + r] = s4.y;
    r = atomicAdd(&g_icnt[d4.z], 1); if (r < CAP) g_csrc[(d4.z << CSH) + r] = s4.z;
    r = atomicAdd(&g_icnt[d4.w], 1); if (r < CAP) g_csrc[(d4.w << CSH) + r] = s4.w;
}

// ------------- per-node: dinv + scaled features; zero pool/cnt
__global__ void k_dinv(const float* __restrict__ x) {
    int i = blockIdx.x * blockDim.x + threadIdx.x;
    float x0 = 0.f, x1 = 0.f, x2 = 0.f;
    if (i < NN) { x0 = x[i * 3 + 0]; x1 = x[i * 3 + 1]; x2 = x[i * 3 + 2]; }
    PDL_WAIT; PDL_FIRE;
    if (i < NN) {
        float d = rsqrtf((float)g_icnt[i] + 1.0f);
        ((float4*)g_xs4)[i] = make_float4(d * x0, d * x1, d * x2, d);
    }
    if (i < NG * H2C) g_pool[i] = 0.f;
    if (i < NG)       g_cnt[i]  = 0.f;
}

// ------- layer 1 aggregate: THREAD per node, int4 bucket reads, no shuffles
// a4[i] = {d*(sum xs + self.x), d*(..y), d*(..z), d}
__global__ void k_ax() {
    PDL_WAIT; PDL_FIRE;
    int i = blockIdx.x * blockDim.x + threadIdx.x;
    if (i >= NN) return;
    int cnt = min(g_icnt[i], CAP);
    const int4* B = (const int4*)&g_csrc[i << CSH];
    const float4* X = (const float4*)g_xs4;

    float ax = 0.f, ay = 0.f, az = 0.f;
    float bx = 0.f, by = 0.f, bz = 0.f;
    float cx = 0.f, cy = 0.f, cz = 0.f;
    float ex = 0.f, ey = 0.f, ez = 0.f;
    int j = 0;
    for (; j + 4 <= cnt; j += 4) {
        int4 s = B[j >> 2];
        float4 v0 = __ldg(&X[s.x]);
        float4 v1 = __ldg(&X[s.y]);
        float4 v2 = __ldg(&X[s.z]);
        float4 v3 = __ldg(&X[s.w]);
        ax += v0.x; ay += v0.y; az += v0.z;
        bx += v1.x; by += v1.y; bz += v1.z;
        cx += v2.x; cy += v2.y; cz += v2.z;
        ex += v3.x; ey += v3.y; ez += v3.z;
    }
    for (; j < cnt; j++) {
        int s = g_csrc[(i << CSH) + j];
        float4 v = __ldg(&X[s]);
        ax += v.x; ay += v.y; az += v.z;
    }
    float4 self = X[i];
    float d = self.w;
    ((float4*)g_a4)[i] = make_float4(
        d * ((ax + bx) + (cx + ex) + self.x),
        d * ((ay + by) + (cy + ey) + self.y),
        d * ((az + bz) + (cz + ez) + self.z),
        d);
}

// ------- layer 1 dense: h1h = fp16( d * relu( a4.xyz @ W1 + b1 ) )
__global__ void k_l1(const float* __restrict__ W1, const float* __restrict__ b1) {
    int t = blockIdx.x * blockDim.x + threadIdx.x;
    int l = t & 31, f = l * 2;
    float w00 = __ldg(&W1[f]),     w01 = __ldg(&W1[64 + f]),     w02 = __ldg(&W1[128 + f]);
    float w10 = __ldg(&W1[f + 1]), w11 = __ldg(&W1[64 + f + 1]), w12 = __ldg(&W1[128 + f + 1]);
    float bb0 = __ldg(&b1[f]), bb1 = __ldg(&b1[f + 1]);
    PDL_WAIT; PDL_FIRE;
    if (t >= NN * 32) return;
    int i = t >> 5;
    float4 a4 = __ldg((const float4*)&g_a4[i * 4]);
    float v0 = a4.x * w00 + a4.y * w01 + a4.z * w02 + bb0;
    float v1 = a4.x * w10 + a4.y * w11 + a4.z * w12 + bb1;
    g_h1h[i * 32 + l] =
        __floats2half2_rn(a4.w * fmaxf(v0, 0.f), a4.w * fmaxf(v1, 0.f));
}

// ------- layer 2 bucket-CSR aggregation (warp per node, 4 fp32 accumulators)
__global__ void __launch_bounds__(128) k_eh() {
    PDL_WAIT; PDL_FIRE;
    int warp = threadIdx.x >> 5;
    int lane = threadIdx.x & 31;
    int node = blockIdx.x * 4 + warp;
    if (node >= NN) return;

    int beg = node << CSH;
    int cnt = min(g_icnt[node], CAP);
    const __half2* H = g_h1h;

    float dn = ((const float4*)g_a4)[node].w;   // dinv of this node

    float2 accA = __half22float2(H[node * 32 + lane]);  // self term
    float2 accB = make_float2(0.f, 0.f);
    float2 accC = make_float2(0.f, 0.f);
    float2 accD = make_float2(0.f, 0.f);

    int j = 0;
    for (; j + 4 <= cnt; j += 4) {
        int s0 = g_csrc[beg + j];
        int s1 = g_csrc[beg + j + 1];
        int s2 = g_csrc[beg + j + 2];
        int s3 = g_csrc[beg + j + 3];
        float2 v0 = __half22float2(H[s0 * 32 + lane]);
        float2 v1 = __half22float2(H[s1 * 32 + lane]);
        float2 v2 = __half22float2(H[s2 * 32 + lane]);
        float2 v3 = __half22float2(H[s3 * 32 + lane]);
        accA.x += v0.x; accA.y += v0.y;
        accB.x += v1.x; accB.y += v1.y;
        accC.x += v2.x; accC.y += v2.y;
        accD.x += v3.x; accD.y += v3.y;
    }
    for (; j < cnt; j++) {
        int s = g_csrc[beg + j];
        float2 v = __half22float2(H[s * 32 + lane]);
        accA.x += v.x; accA.y += v.y;
    }
    g_aggh2[node * 32 + lane] = __floats2half2_rn(
        dn * ((accA.x + accB.x) + (accC.x + accD.x)),
        dn * ((accA.y + accB.y) + (accC.y + accD.y)));
}

// ---- layer-2 dense via tensor cores + fused mean-pool (3 warps/block, striding)
#define L2PAD 130
__global__ void __launch_bounds__(96)
k_l2t(const float* __restrict__ W2, const float* __restrict__ b2,
      const int* __restrict__ batch) {
    __shared__ __half2 sB[128 * 33];          // W2 fragments: pair(k,k+1) per col
    __shared__ float   sC[3][16 * L2PAD];     // per-warp C staging

    int tid = threadIdx.x;
    for (int idx = tid; idx < 128 * 32; idx += 96) {
        int j = idx >> 7;          // k-pair 0..31
        int n = idx & 127;         // output column
        sB[n * 33 + j] =
            __floats2half2_rn(W2[(2 * j) * H2C + n], W2[(2 * j + 1) * H2C + n]);
    }
    int warp = tid >> 5, lane = tid & 31;
    int g = lane >> 2, t = lane & 3;
    float bias0 = __ldg(&b2[lane]);
    float bias1 = __ldg(&b2[lane + 32]);
    float bias2 = __ldg(&b2[lane + 64]);
    float bias3 = __ldg(&b2[lane + 96]);
    __syncthreads();
    PDL_WAIT; PDL_FIRE;

    float* myC = sC[warp];
    const unsigned* A = (const unsigned*)g_aggh2;
    int wstride = gridDim.x * 3;

    for (int tile = blockIdx.x * 3 + warp; tile < NTILES; tile += wstride) {
        int node0 = tile * 16;

        unsigned a[4][4];
        {
            int r0 = (node0 + g) * 32, r1 = (node0 + g + 8) * 32;
#pragma unroll
            for (int kk = 0; kk < 4; kk++) {
                a[kk][0] = A[r0 + kk * 8 + t];
                a[kk][1] = A[r1 + kk * 8 + t];
                a[kk][2] = A[r0 + kk * 8 + t + 4];
                a[kk][3] = A[r1 + kk * 8 + t + 4];
            }
        }
        __syncwarp();   // sC WAR across tile iterations
#pragma unroll
        for (int nt = 0; nt < 16; nt++) {
            float c0 = 0.f, c1 = 0.f, c2 = 0.f, c3 = 0.f;
            int n = nt * 8 + g;
#pragma unroll
            for (int kk = 0; kk < 4; kk++) {
                unsigned b0 = *(const unsigned*)&sB[n * 33 + kk * 8 + t];
                unsigned b1 = *(const unsigned*)&sB[n * 33 + kk * 8 + t + 4];
                asm volatile(
                    "mma.sync.aligned.m16n8k16.row.col.f32.f16.f16.f32 "
                    "{%0,%1,%2,%3}, {%4,%5,%6,%7}, {%8,%9}, {%0,%1,%2,%3};"
                    : "+f"(c0), "+f"(c1), "+f"(c2), "+f"(c3)
                    : "r"(a[kk][0]), "r"(a[kk][1]), "r"(a[kk][2]), "r"(a[kk][3]),
                      "r"(b0), "r"(b1));
            }
            int col = nt * 8 + t * 2;
            *(float2*)&myC[g * L2PAD + col]       = make_float2(c0, c1);
            *(float2*)&myC[(g + 8) * L2PAD + col] = make_float2(c2, c3);
        }
        __syncwarp();

        float p0 = 0.f, p1 = 0.f, p2 = 0.f, p3 = 0.f, cntacc = 0.f;
        int cur_g = batch[node0];
#pragma unroll
        for (int r = 0; r < 16; r++) {
            int gid = batch[node0 + r];
            if (gid != cur_g) {
                red_add_f(&g_pool[cur_g * H2C + lane],      p0);
                red_add_f(&g_pool[cur_g * H2C + lane + 32], p1);
                red_add_f(&g_pool[cur_g * H2C + lane + 64], p2);
                red_add_f(&g_pool[cur_g * H2C + lane + 96], p3);
                if (lane == 0) red_add_f(&g_cnt[cur_g], cntacc);
                p0 = p1 = p2 = p3 = 0.f; cntacc = 0.f; cur_g = gid;
            }
            const float* row = &myC[r * L2PAD];
            p0 += fmaxf(row[lane]      + bias0, 0.f);
            p1 += fmaxf(row[lane + 32] + bias1, 0.f);
            p2 += fmaxf(row[lane + 64] + bias2, 0.f);
            p3 += fmaxf(row[lane + 96] + bias3, 0.f);
            cntacc += 1.f;
        }
        red_add_f(&g_pool[cur_g * H2C + lane],      p0);
        red_add_f(&g_pool[cur_g * H2C + lane + 32], p1);
        red_add_f(&g_pool[cur_g * H2C + lane + 64], p2);
        red_add_f(&g_pool[cur_g * H2C + lane + 96], p3);
        if (lane == 0) red_add_f(&g_cnt[cur_g], cntacc);
    }
}

// ---------------------------------------- final: out = (pool/cnt)@Wfc + bfc
__global__ void k_out(const float* __restrict__ Wfc, const float* __restrict__ bfc,
                      float* __restrict__ out) {
    int t = blockIdx.x * blockDim.x + threadIdx.x;
    int o = t & 1;
    float bias = __ldg(&bfc[o]);
    PDL_WAIT;
    if (t >= NG * OUTC) return;
    int g = t >> 1;
    float inv = 1.0f / fmaxf(g_cnt[g], 1.0f);
    float s = 0.f;
#pragma unroll
    for (int k = 0; k < H2C; k++)
        s = fmaf(g_pool[g * H2C + k], __ldg(&Wfc[k * OUTC + o]), s);
    out[t] = s * inv + bias;
}

// ---------------- PDL launch helper ----------------
template <typename K, typename... Args>
static void launch_pdl(K k, int grid, int block, Args... args) {
    cudaLaunchConfig_t cfg = {};
    cfg.gridDim = dim3(grid, 1, 1);
    cfg.blockDim = dim3(block, 1, 1);
    cfg.dynamicSmemBytes = 0;
    cfg.stream = 0;
    cudaLaunchAttribute at[1];
    at[0].id = cudaLaunchAttributeProgrammaticStreamSerialization;
    at[0].val.programmaticStreamSerializationAllowed = 1;
    cfg.attrs = at;
    cfg.numAttrs = 1;
    cudaLaunchKernelEx(&cfg, k, args...);
}

extern "C" void kernel_launch(void* const* d_in, const int* in_sizes, int n_in,
                              void* d_out, int out_size) {
    const float* x   = (const float*)d_in[0];
    const int*   ei  = (const int*)d_in[1];   // [2, E] int32
    const int*   bat = (const int*)d_in[2];   // [N] int32
    const float* W1  = (const float*)d_in[3];
    const float* b1  = (const float*)d_in[4];
    const float* W2  = (const float*)d_in[5];
    const float* b2  = (const float*)d_in[6];
    const float* Wfc = (const float*)d_in[7];
    const float* bfc = (const float*)d_in[8];
    float*       out = (float*)d_out;

    const int* src = ei;
    const int* dst = ei + NE;

    const int T = 256;
    k_zero<<<(NN / 4 + T - 1) / T, T>>>();
    launch_pdl(k_cf,   (NE / 4 + T - 1) / T, T, src, dst);
    launch_pdl(k_dinv, (NN + T - 1) / T, T, x);
    launch_pdl(k_ax,   (NN + T - 1) / T, T);
    launch_pdl(k_l1,   (NN * 32 + T - 1) / T, T, W1, b1);
    launch_pdl(k_eh,   NN / 4, 128);
    launch_pdl(k_l2t,  740, 96, W2, b2, bat);
    launch_pdl(k_out,  (NG * OUTC + T - 1) / T, T, Wfc, bfc, out);
}

// round 16
// speedup vs baseline: 1.0147x; 1.0147x over previous
#include <cuda_runtime.h>
#include <cuda_fp16.h>
#include <cuda_bf16.h>

#define NN 100000
#define NE 1600000
#define NG 512
#define H1C 64
#define H2C 128
#define OUTC 2
#define CAP 128          // bucket capacity per node (max in-degree guard)
#define CSH 7            // log2(CAP)
#define NTILES 6250      // NN / 16

#define PDL_WAIT asm volatile("griddepcontrol.wait;" ::: "memory")
#define PDL_FIRE asm volatile("griddepcontrol.launch_dependents;")

// ---------------- scratch (__device__ globals) ----------------
__device__ __align__(16) int     g_icnt[NN];         // in-degree
__device__ __align__(16) int     g_csrc[NN * CAP];   // bucket CSR: src per slot
__device__ __align__(16) float   g_xs4 [NN * 4];     // {d*x0, d*x1, d*x2, d}
__device__ __align__(16) float   g_a4  [NN * 4];     // {d*agg0, d*agg1, d*agg2, d}
__device__ __align__(16) __half2 g_h1h [NN * 32];    // fp16 dinv-scaled relu(l1)
__device__ __align__(16) __half2 g_aggh2[NN * 32];   // fp16 layer-2 aggregate
__device__ __align__(16) float   g_pool[NG * H2C];
__device__ __align__(16) float   g_cnt [NG];

__device__ __forceinline__ void red_add_f(float* addr, float v) {
    asm volatile("red.global.add.f32 [%0], %1;" :: "l"(addr), "f"(v) : "memory");
}

// -------------------------------- zero in-degree counters
__global__ void k_zero() {
    PDL_FIRE;
    int i = blockIdx.x * blockDim.x + threadIdx.x;
    if (i < NN / 4) ((int4*)g_icnt)[i] = make_int4(0, 0, 0, 0);
}

// ------------- fused count + bucket fill (ONE edge pass)
__global__ void k_cf(const int* __restrict__ src, const int* __restrict__ dst) {
    int i = blockIdx.x * blockDim.x + threadIdx.x;
    int4 d4 = make_int4(0, 0, 0, 0), s4 = make_int4(0, 0, 0, 0);
    bool ok = (i < NE / 4);
    if (ok) { d4 = ((const int4*)dst)[i]; s4 = ((const int4*)src)[i]; }
    PDL_WAIT; PDL_FIRE;
    if (!ok) return;
    int r;
    r = atomicAdd(&g_icnt[d4.x], 1); if (r < CAP) g_csrc[(d4.x << CSH) + r] = s4.x;
    r = atomicAdd(&g_icnt[d4.y], 1); if (r < CAP) g_csrc[(d4.y << CSH) + r] = s4.y;
    r = atomicAdd(&g_icnt[d4.z], 1); if (r < CAP) g_csrc[(d4.z << CSH) + r] = s4.z;
    r = atomicAdd(&g_icnt[d4.w], 1); if (r < CAP) g_csrc[(d4.w << CSH) + r] = s4.w;
}

// ------------- per-node: dinv + scaled features; zero pool/cnt
__global__ void k_dinv(const float* __restrict__ x) {
    int i = blockIdx.x * blockDim.x + threadIdx.x;
    float x0 = 0.f, x1 = 0.f, x2 = 0.f;
    if (i < NN) { x0 = x[i * 3 + 0]; x1 = x[i * 3 + 1]; x2 = x[i * 3 + 2]; }
    PDL_WAIT; PDL_FIRE;
    if (i < NN) {
        float d = rsqrtf((float)g_icnt[i] + 1.0f);
        ((float4*)g_xs4)[i] = make_float4(d * x0, d * x1, d * x2, d);
    }
    if (i < NG * H2C) g_pool[i] = 0.f;
    if (i < NG)       g_cnt[i]  = 0.f;
}

// ------- layer 1 aggregate: TWO threads per node (pair splits int4 groups)
// a4[i] = {d*(sum xs + self.x), d*(..y), d*(..z), d}
__global__ void k_ax() {
    PDL_WAIT; PDL_FIRE;
    int t = blockIdx.x * blockDim.x + threadIdx.x;
    int i = t >> 1;          // node
    int q = t & 1;           // pair half
    if (i >= NN) return;
    int cnt = min(g_icnt[i], CAP);
    int nfull = cnt >> 2;    // complete int4 groups
    const int4* B = (const int4*)&g_csrc[i << CSH];
    const float4* X = (const float4*)g_xs4;

    float ax = 0.f, ay = 0.f, az = 0.f;
    float bx = 0.f, by = 0.f, bz = 0.f;
    // thread q processes int4 groups q, q+2, q+4, ...
    for (int j4 = q; j4 < nfull; j4 += 2) {
        int4 s = B[j4];
        float4 v0 = __ldg(&X[s.x]);
        float4 v1 = __ldg(&X[s.y]);
        float4 v2 = __ldg(&X[s.z]);
        float4 v3 = __ldg(&X[s.w]);
        ax += v0.x + v1.x; ay += v0.y + v1.y; az += v0.z + v1.z;
        bx += v2.x + v3.x; by += v2.y + v3.y; bz += v2.z + v3.z;
    }
    // scalar tail (indices nfull*4 .. cnt-1) handled by q==1
    if (q) {
        for (int j = nfull << 2; j < cnt; j++) {
            int s = g_csrc[(i << CSH) + j];
            float4 v = __ldg(&X[s]);
            ax += v.x; ay += v.y; az += v.z;
        }
    }
    float sx = ax + bx, sy = ay + by, sz = az + bz;
    // combine pair partials (lanes 2k / 2k+1)
    sx += __shfl_xor_sync(0xffffffffu, sx, 1);
    sy += __shfl_xor_sync(0xffffffffu, sy, 1);
    sz += __shfl_xor_sync(0xffffffffu, sz, 1);
    if (q == 0) {
        float4 self = X[i];
        float d = self.w;
        ((float4*)g_a4)[i] = make_float4(
            d * (sx + self.x), d * (sy + self.y), d * (sz + self.z), d);
    }
}

// ------- layer 1 dense: h1h = fp16( d * relu( a4.xyz @ W1 + b1 ) )
__global__ void k_l1(const float* __restrict__ W1, const float* __restrict__ b1) {
    int t = blockIdx.x * blockDim.x + threadIdx.x;
    int l = t & 31, f = l * 2;
    float w00 = __ldg(&W1[f]),     w01 = __ldg(&W1[64 + f]),     w02 = __ldg(&W1[128 + f]);
    float w10 = __ldg(&W1[f + 1]), w11 = __ldg(&W1[64 + f + 1]), w12 = __ldg(&W1[128 + f + 1]);
    float bb0 = __ldg(&b1[f]), bb1 = __ldg(&b1[f + 1]);
    PDL_WAIT; PDL_FIRE;
    if (t >= NN * 32) return;
    int i = t >> 5;
    float4 a4 = __ldg((const float4*)&g_a4[i * 4]);
    float v0 = a4.x * w00 + a4.y * w01 + a4.z * w02 + bb0;
    float v1 = a4.x * w10 + a4.y * w11 + a4.z * w12 + bb1;
    g_h1h[i * 32 + l] =
        __floats2half2_rn(a4.w * fmaxf(v0, 0.f), a4.w * fmaxf(v1, 0.f));
}

// ------- layer 2 bucket-CSR aggregation (warp per node, 4 fp32 accumulators)
__global__ void __launch_bounds__(128) k_eh() {
    PDL_WAIT; PDL_FIRE;
    int warp = threadIdx.x >> 5;
    int lane = threadIdx.x & 31;
    int node = blockIdx.x * 4 + warp;
    if (node >= NN) return;

    int beg = node << CSH;
    int cnt = min(g_icnt[node], CAP);
    const __half2* H = g_h1h;

    float dn = ((const float4*)g_a4)[node].w;   // dinv of this node

    float2 accA = __half22float2(H[node * 32 + lane]);  // self term
    float2 accB = make_float2(0.f, 0.f);
    float2 accC = make_float2(0.f, 0.f);
    float2 accD = make_float2(0.f, 0.f);

    int j = 0;
    for (; j + 4 <= cnt; j += 4) {
        int s0 = g_csrc[beg + j];
        int s1 = g_csrc[beg + j + 1];
        int s2 = g_csrc[beg + j + 2];
        int s3 = g_csrc[beg + j + 3];
        float2 v0 = __half22float2(H[s0 * 32 + lane]);
        float2 v1 = __half22float2(H[s1 * 32 + lane]);
        float2 v2 = __half22float2(H[s2 * 32 + lane]);
        float2 v3 = __half22float2(H[s3 * 32 + lane]);
        accA.x += v0.x; accA.y += v0.y;
        accB.x += v1.x; accB.y += v1.y;
        accC.x += v2.x; accC.y += v2.y;
        accD.x += v3.x; accD.y += v3.y;
    }
    for (; j < cnt; j++) {
        int s = g_csrc[beg + j];
        float2 v = __half22float2(H[s * 32 + lane]);
        accA.x += v.x; accA.y += v.y;
    }
    g_aggh2[node * 32 + lane] = __floats2half2_rn(
        dn * ((accA.x + accB.x) + (accC.x + accD.x)),
        dn * ((accA.y + accB.y) + (accC.y + accD.y)));
}

// ---- layer-2 dense via tensor cores + fused mean-pool (3 warps/block, striding)
#define L2PAD 130
__global__ void __launch_bounds__(96)
k_l2t(const float* __restrict__ W2, const float* __restrict__ b2,
      const int* __restrict__ batch) {
    __shared__ __half2 sB[128 * 33];          // W2 fragments: pair(k,k+1) per col
    __shared__ float   sC[3][16 * L2PAD];     // per-warp C staging

    int tid = threadIdx.x;
    for (int idx = tid; idx < 128 * 32; idx += 96) {
        int j = idx >> 7;          // k-pair 0..31
        int n = idx & 127;         // output column
        sB[n * 33 + j] =
            __floats2half2_rn(W2[(2 * j) * H2C + n], W2[(2 * j + 1) * H2C + n]);
    }
    int warp = tid >> 5, lane = tid & 31;
    int g = lane >> 2, t = lane & 3;
    float bias0 = __ldg(&b2[lane]);
    float bias1 = __ldg(&b2[lane + 32]);
    float bias2 = __ldg(&b2[lane + 64]);
    float bias3 = __ldg(&b2[lane + 96]);
    __syncthreads();
    PDL_WAIT; PDL_FIRE;

    float* myC = sC[warp];
    const unsigned* A = (const unsigned*)g_aggh2;
    int wstride = gridDim.x * 3;

    for (int tile = blockIdx.x * 3 + warp; tile < NTILES; tile += wstride) {
        int node0 = tile * 16;

        unsigned a[4][4];
        {
            int r0 = (node0 + g) * 32, r1 = (node0 + g + 8) * 32;
#pragma unroll
            for (int kk = 0; kk < 4; kk++) {
                a[kk][0] = A[r0 + kk * 8 + t];
                a[kk][1] = A[r1 + kk * 8 + t];
                a[kk][2] = A[r0 + kk * 8 + t + 4];
                a[kk][3] = A[r1 + kk * 8 + t + 4];
            }
        }
        __syncwarp();   // sC WAR across tile iterations
#pragma unroll
        for (int nt = 0; nt < 16; nt++) {
            float c0 = 0.f, c1 = 0.f, c2 = 0.f, c3 = 0.f;
            int n = nt * 8 + g;
#pragma unroll
            for (int kk = 0; kk < 4; kk++) {
                unsigned b0 = *(const unsigned*)&sB[n * 33 + kk * 8 + t];
                unsigned b1 = *(const unsigned*)&sB[n * 33 + kk * 8 + t + 4];
                asm volatile(
                    "mma.sync.aligned.m16n8k16.row.col.f32.f16.f16.f32 "
                    "{%0,%1,%2,%3}, {%4,%5,%6,%7}, {%8,%9}, {%0,%1,%2,%3};"
                    : "+f"(c0), "+f"(c1), "+f"(c2), "+f"(c3)
                    : "r"(a[kk][0]), "r"(a[kk][1]), "r"(a[kk][2]), "r"(a[kk][3]),
                      "r"(b0), "r"(b1));
            }
            int col = nt * 8 + t * 2;
            *(float2*)&myC[g * L2PAD + col]       = make_float2(c0, c1);
            *(float2*)&myC[(g + 8) * L2PAD + col] = make_float2(c2, c3);
        }
        __syncwarp();

        float p0 = 0.f, p1 = 0.f, p2 = 0.f, p3 = 0.f, cntacc = 0.f;
        int cur_g = batch[node0];
#pragma unroll
        for (int r = 0; r < 16; r++) {
            int gid = batch[node0 + r];
            if (gid != cur_g) {
                red_add_f(&g_pool[cur_g * H2C + lane],      p0);
                red_add_f(&g_pool[cur_g * H2C + lane + 32], p1);
                red_add_f(&g_pool[cur_g * H2C + lane + 64], p2);
                red_add_f(&g_pool[cur_g * H2C + lane + 96], p3);
                if (lane == 0) red_add_f(&g_cnt[cur_g], cntacc);
                p0 = p1 = p2 = p3 = 0.f; cntacc = 0.f; cur_g = gid;
            }
            const float* row = &myC[r * L2PAD];
            p0 += fmaxf(row[lane]      + bias0, 0.f);
            p1 += fmaxf(row[lane + 32] + bias1, 0.f);
            p2 += fmaxf(row[lane + 64] + bias2, 0.f);
            p3 += fmaxf(row[lane + 96] + bias3, 0.f);
            cntacc += 1.f;
        }
        red_add_f(&g_pool[cur_g * H2C + lane],      p0);
        red_add_f(&g_pool[cur_g * H2C + lane + 32], p1);
        red_add_f(&g_pool[cur_g * H2C + lane + 64], p2);
        red_add_f(&g_pool[cur_g * H2C + lane + 96], p3);
        if (lane == 0) red_add_f(&g_cnt[cur_g], cntacc);
    }
}

// ---------------------------------------- final: out = (pool/cnt)@Wfc + bfc
__global__ void k_out(const float* __restrict__ Wfc, const float* __restrict__ bfc,
                      float* __restrict__ out) {
    int t = blockIdx.x * blockDim.x + threadIdx.x;
    int o = t & 1;
    float bias = __ldg(&bfc[o]);
    PDL_WAIT;
    if (t >= NG * OUTC) return;
    int g = t >> 1;
    float inv = 1.0f / fmaxf(g_cnt[g], 1.0f);
    float s = 0.f;
#pragma unroll
    for (int k = 0; k < H2C; k++)
        s = fmaf(g_pool[g * H2C + k], __ldg(&Wfc[k * OUTC + o]), s);
    out[t] = s * inv + bias;
}

// ---------------- PDL launch helper ----------------
template <typename K, typename... Args>
static void launch_pdl(K k, int grid, int block, Args... args) {
    cudaLaunchConfig_t cfg = {};
    cfg.gridDim = dim3(grid, 1, 1);
    cfg.blockDim = dim3(block, 1, 1);
    cfg.dynamicSmemBytes = 0;
    cfg.stream = 0;
    cudaLaunchAttribute at[1];
    at[0].id = cudaLaunchAttributeProgrammaticStreamSerialization;
    at[0].val.programmaticStreamSerializationAllowed = 1;
    cfg.attrs = at;
    cfg.numAttrs = 1;
    cudaLaunchKernelEx(&cfg, k, args...);
}

extern "C" void kernel_launch(void* const* d_in, const int* in_sizes, int n_in,
                              void* d_out, int out_size) {
    const float* x   = (const float*)d_in[0];
    const int*   ei  = (const int*)d_in[1];   // [2, E] int32
    const int*   bat = (const int*)d_in[2];   // [N] int32
    const float* W1  = (const float*)d_in[3];
    const float* b1  = (const float*)d_in[4];
    const float* W2  = (const float*)d_in[5];
    const float* b2  = (const float*)d_in[6];
    const float* Wfc = (const float*)d_in[7];
    const float* bfc = (const float*)d_in[8];
    float*       out = (float*)d_out;

    const int* src = ei;
    const int* dst = ei + NE;

    const int T = 256;
    k_zero<<<(NN / 4 + T - 1) / T, T>>>();
    launch_pdl(k_cf,   (NE / 4 + T - 1) / T, T, src, dst);
    launch_pdl(k_dinv, (NN + T - 1) / T, T, x);
    launch_pdl(k_ax,   (NN * 2 + T - 1) / T, T);
    launch_pdl(k_l1,   (NN * 32 + T - 1) / T, T, W1, b1);
    launch_pdl(k_eh,   NN / 4, 128);
    launch_pdl(k_l2t,  740, 96, W2, b2, bat);
    launch_pdl(k_out,  (NG * OUTC + T - 1) / T, T, Wfc, bfc, out);
}